// round 1
// baseline (speedup 1.0000x reference)
#include <cuda_runtime.h>
#include <math.h>

// Problem constants
#define BATCH 4096
#define DIM   64

// Tiling
#define ROWS_PER_WARP   4
#define WARPS_PER_BLOCK 4
#define THREADS         (WARPS_PER_BLOCK * 32)
#define ROWS_PER_BLOCK  (ROWS_PER_WARP * WARPS_PER_BLOCK)   // 16
#define NBLOCKS         (BATCH / ROWS_PER_BLOCK)            // 256

#define WPITCH 68   // floats per W row in shared: 68*4B=272B, 16B aligned, conflict-free float4 reads

#define MAX_IT 200
#define DTOL   5e-6f

// Accurate tanh independent of --use_fast_math lowering of tanhf.
// __expf is MUFU.EX2-based (~2^-21 rel err), so |err| ~1e-6 absolute: the
// induced fixed-point shift is ~1e-6, far inside the 1e-3 rel_err budget.
__device__ __forceinline__ float my_tanh(float a) {
    float aa = fabsf(a);
    float e  = __expf(-2.0f * aa);          // in (0, 1]
    float t  = (1.0f - e) / (1.0f + e);     // |tanh(a)|
    return copysignf(t, a);
}

__global__ void __launch_bounds__(THREADS)
tanh_fixed_point_kernel(const float* __restrict__ x,
                        const float* __restrict__ W,
                        float* __restrict__ out)
{
    __shared__ float Wsh[DIM * WPITCH];
    __shared__ float zsh[WARPS_PER_BLOCK][ROWS_PER_WARP][DIM];

    const int tid  = threadIdx.x;
    const int lane = tid & 31;
    const int warp = tid >> 5;

    // Stage W into shared: Wsh[i*WPITCH + j] = W[i*DIM + j]
    for (int idx = tid; idx < DIM * DIM; idx += THREADS) {
        int i = idx >> 6;
        int j = idx & 63;
        Wsh[i * WPITCH + j] = W[idx];
    }
    __syncthreads();

    const int row0 = blockIdx.x * ROWS_PER_BLOCK + warp * ROWS_PER_WARP;

    // Per-lane state: lane holds components (lane) and (lane+32) of each row.
    float xr[ROWS_PER_WARP][2];
    float z [ROWS_PER_WARP][2];
    #pragma unroll
    for (int r = 0; r < ROWS_PER_WARP; r++) {
        xr[r][0] = x[(row0 + r) * DIM + lane];
        xr[r][1] = x[(row0 + r) * DIM + lane + 32];
        z[r][0]  = my_tanh(xr[r][0]);   // z0 = tanh(x)
        z[r][1]  = my_tanh(xr[r][1]);
    }

    // This lane's two W rows (i = lane, i = lane+32), as float4 (conflict-free: pitch 17 float4)
    const float4* Wr0 = reinterpret_cast<const float4*>(&Wsh[lane * WPITCH]);
    const float4* Wr1 = reinterpret_cast<const float4*>(&Wsh[(lane + 32) * WPITCH]);

    for (int it = 0; it < MAX_IT; it++) {
        // Stage current z of this warp's 4 rows into shared
        #pragma unroll
        for (int r = 0; r < ROWS_PER_WARP; r++) {
            zsh[warp][r][lane]      = z[r][0];
            zsh[warp][r][lane + 32] = z[r][1];
        }
        __syncwarp();

        float acc[ROWS_PER_WARP][2];
        #pragma unroll
        for (int r = 0; r < ROWS_PER_WARP; r++) {
            acc[r][0] = xr[r][0];
            acc[r][1] = xr[r][1];
        }

        // zl_i = x_i + sum_j W[i][j] * z[j]; W float4 reused across the 4 rows
        #pragma unroll
        for (int jc = 0; jc < DIM / 4; jc++) {
            float4 w0 = Wr0[jc];
            float4 w1 = Wr1[jc];
            #pragma unroll
            for (int r = 0; r < ROWS_PER_WARP; r++) {
                float4 zv = reinterpret_cast<const float4*>(zsh[warp][r])[jc]; // broadcast
                acc[r][0] = fmaf(w0.x, zv.x, acc[r][0]);
                acc[r][0] = fmaf(w0.y, zv.y, acc[r][0]);
                acc[r][0] = fmaf(w0.z, zv.z, acc[r][0]);
                acc[r][0] = fmaf(w0.w, zv.w, acc[r][0]);
                acc[r][1] = fmaf(w1.x, zv.x, acc[r][1]);
                acc[r][1] = fmaf(w1.y, zv.y, acc[r][1]);
                acc[r][1] = fmaf(w1.z, zv.z, acc[r][1]);
                acc[r][1] = fmaf(w1.w, zv.w, acc[r][1]);
            }
        }

        // z_new = tanh(zl); track max |delta| for convergence
        bool conv = true;
        #pragma unroll
        for (int r = 0; r < ROWS_PER_WARP; r++) {
            float n0 = my_tanh(acc[r][0]);
            float n1 = my_tanh(acc[r][1]);
            conv = conv && (fabsf(n0 - z[r][0]) < DTOL) && (fabsf(n1 - z[r][1]) < DTOL);
            z[r][0] = n0;
            z[r][1] = n1;
        }

        __syncwarp();  // all lanes done reading zsh before next store
        if (__all_sync(0xffffffffu, conv)) break;
    }

    #pragma unroll
    for (int r = 0; r < ROWS_PER_WARP; r++) {
        out[(row0 + r) * DIM + lane]      = z[r][0];
        out[(row0 + r) * DIM + lane + 32] = z[r][1];
    }
}

extern "C" void kernel_launch(void* const* d_in, const int* in_sizes, int n_in,
                              void* d_out, int out_size)
{
    const float* x = (const float*)d_in[0];   // [4096, 64]
    const float* W = (const float*)d_in[1];   // [64, 64]
    float* out = (float*)d_out;               // [4096, 64]
    (void)in_sizes; (void)n_in; (void)out_size;

    tanh_fixed_point_kernel<<<NBLOCKS, THREADS>>>(x, W, out);
}